// round 10
// baseline (speedup 1.0000x reference)
#include <cuda_runtime.h>
#include <cuda_bf16.h>
#include <math.h>

#define BSN 32
#define QN 1024
#define KN 96
#define QN1 (QN + 1)
#define INFV 1000000000.0f
#define NELEM (QN * 3)   // 98304 per input
#define NT 128
#define CPT 8
#define NW (NT / 32)
#define FINF __int_as_float(0x7F800000)

__device__ __forceinline__ bool probe_is_labels(const float* x) {
    const int qs[6] = {0, 13, 95, 96, 511, 1023};
    #pragma unroll
    for (int t = 0; t < 6; t++) {
        float v = x[qs[t] * 3];
        if (v != 0.0f && v != 1.0f) return false;
    }
    return true;
}

// Bit-exact replica of XLA:CPU GenerateVF32Exp (proven R6).
__device__ __forceinline__ float xla_cpu_expf(float x_in) {
    float x = fmaxf(fminf(x_in, 88.3762626647950f), -88.3762626647949f);
    float fx = floorf(__fmaf_rn(x, 1.44269504088896341f, 0.5f));
    float tmp = __fmul_rn(0.693359375f, fx);
    float z   = __fmul_rn(-2.12194440e-4f, fx);
    x = __fsub_rn(x, tmp);
    x = __fsub_rn(x, z);
    float x2 = __fmul_rn(x, x);
    float y = __fmaf_rn(x, 1.9875691500E-4f, 1.3981999507E-3f);
    y = __fmaf_rn(y, x, 8.3334519073E-3f);
    y = __fmaf_rn(y, x, 4.1665795894E-2f);
    y = __fmaf_rn(y, x, 1.6666665459E-1f);
    y = __fmaf_rn(y, x, 5.0000001201E-1f);
    y = __fmaf_rn(y, x2, x);
    y = __fadd_rn(y, 1.0f);
    int k = (int)fx;
    float scale = __int_as_float((k + 127) << 23);
    return fmaxf(__fmul_rn(y, scale), x_in);
}

__device__ __forceinline__ float xla_sigmoid(float x) {
    float e = xla_cpu_expf(-x);
    return __fdiv_rn(1.0f, __fadd_rn(1.0f, e));
}

// monotone float -> u32 map (no NaN ties / -0.0 in our domain)
__device__ __forceinline__ unsigned int fmap(float f) {
    unsigned int u = __float_as_uint(f);
    return (u & 0x80000000u) ? ~u : (u | 0x80000000u);
}
__device__ __forceinline__ float funmap(unsigned int m) {
    unsigned int u = (m & 0x80000000u) ? (m & 0x7FFFFFFFu) : ~m;
    return __uint_as_float(u);
}

__device__ __forceinline__ unsigned int redux_min_u32(unsigned int x) {
    unsigned int r;
    asm("redux.sync.min.u32 %0, %1, 0xffffffff;" : "=r"(r) : "r"(x));
    return r;
}

__global__ __launch_bounds__(NT, 1)
void hungarian_kernel(const float* __restrict__ in0,
                      const float* __restrict__ in1,
                      float* __restrict__ out,
                      int write_col_ind) {
    __shared__ float  u_sh[KN + 1];
    __shared__ int    p_sh[QN1];
    __shared__ int    way_sh[QN1];
    __shared__ float  t1_sh[KN], t2_sh[KN];
    __shared__ float4 prow[QN1];            // {p (int bits), u[p], t1[p-1], t2[p-1]}
    __shared__ unsigned long long redk[2][NW];   // double-buffered, tag in bit0
    __shared__ int    a_sh[KN];
    __shared__ int    swap_flag;

    const int tid  = threadIdx.x;
    const int b    = blockIdx.x;
    const int lane = tid & 31;
    const int wid  = tid >> 5;

    if (tid == 0) {
        bool l0 = probe_is_labels(in0);
        bool l1 = probe_is_labels(in1);
        swap_flag = (l0 && !l1) ? 1 : 0;
    }
    if (tid < 2 * NW) ((unsigned long long*)redk)[tid] = 1ull;  // tag=1 sentinel
    __syncthreads();
    const float* L  = (swap_flag ? in1 : in0) + (size_t)b * NELEM;  // logits
    const float* Lb = (swap_flag ? in0 : in1) + (size_t)b * NELEM;  // labels

    // Per-thread columns: jc = tid*CPT + c + 1 (contiguous)
    float negorig[CPT], np[CPT], b1r[CPT], b2r[CPT], vr[CPT], minv[CPT], uacc[CPT];
    int   rowc[CPT];
    #pragma unroll
    for (int c = 0; c < CPT; c++) {
        int q = tid * CPT + c;
        negorig[c] = -xla_sigmoid(L[q * 3 + 0]);
        b1r[c] = L[q * 3 + 1];
        b2r[c] = L[q * 3 + 2];
        vr[c]  = 0.0f;
    }
    if (tid < KN) {
        t1_sh[tid] = Lb[tid * 3 + 1];
        t2_sh[tid] = Lb[tid * 3 + 2];
        u_sh[tid + 1] = 0.0f;
    }
    if (tid == 0) u_sh[0] = 0.0f;
    for (int idx = tid; idx < QN1; idx += NT) p_sh[idx] = 0;
    __syncthreads();

    unsigned int gs = 0;   // global step counter (par = gs&1, tag = (gs>>1)&1)

    for (int i = 1; i <= KN; i++) {
        // rebuild prow: p and u are frozen during a path (proven R7)
        for (int idx = tid; idx < QN; idx += NT) {
            int jj = idx + 1;
            int pi = p_sh[jj];
            float4 r;
            r.x = __int_as_float(pi);
            if (pi > 0) { r.y = u_sh[pi]; r.z = t1_sh[pi - 1]; r.w = t2_sh[pi - 1]; }
            else        { r.y = 0.0f; r.z = 0.0f; r.w = 0.0f; }
            prow[jj] = r;
        }
        __syncthreads();   // prow must be visible before any in-path read

        #pragma unroll
        for (int c = 0; c < CPT; c++) { minv[c] = INFV; np[c] = negorig[c]; }
        unsigned int usedm = 0;
        int   j0 = 0, i0 = i;
        float ui0 = u_sh[i];
        float tt1 = t1_sh[i - 1], tt2 = t2_sh[i - 1];
        float u0acc = ui0;     // column 0 (always used), tracked by tid 0

        while (true) {
            // mark used: owner poisons working copies (np/minv = +Inf)
            unsigned int t = (unsigned int)(j0 - 1 - tid * CPT);
            if (t < CPT) {
                usedm |= (1u << t);
                #pragma unroll
                for (int c = 0; c < CPT; c++)
                    if (c == (int)t) {
                        np[c] = FINF; minv[c] = FINF;
                        uacc[c] = ui0; rowc[c] = i0;
                    }
            }

            // compute candidates (used cols give cur = +Inf)
            #pragma unroll
            for (int c = 0; c < CPT; c++) {
                float d1 = b1r[c] - tt1;
                float d2 = b2r[c] - tt2;
                float s  = fabsf(d1) + fabsf(d2);
                float cur = ((np[c] + s) - ui0) - vr[c];
                if (cur < minv[c]) way_sh[tid * CPT + c + 1] = j0;
                minv[c] = fminf(minv[c], cur);
            }
            // thread-best: exact min tree (order-free, no rounding)
            float m01 = fminf(minv[0], minv[1]);
            float m23 = fminf(minv[2], minv[3]);
            float m45 = fminf(minv[4], minv[5]);
            float m67 = fminf(minv[6], minv[7]);
            float bestv = fminf(fminf(m01, m23), fminf(m45, m67));
            // local argmin (first c), hoisted off the inter-redux path
            unsigned int lj = 0x7FFFFFFFu;
            #pragma unroll
            for (int c = CPT - 1; c >= 0; c--)
                if (minv[c] == bestv) lj = (unsigned int)(tid * CPT + c + 1);

            unsigned int mb   = fmap(bestv);
            unsigned int wmin = redux_min_u32(mb);
            unsigned int jc2  = (mb == wmin) ? lj : 0x7FFFFFFFu;
            unsigned int jmin = redux_min_u32(jc2);

            int par = (int)(gs & 1u);
            unsigned long long tag = (unsigned long long)((gs >> 1) & 1u);
            gs++;
            volatile unsigned long long* rk = &redk[par][0];
            if (lane == 0)
                rk[wid] = ((unsigned long long)wmin << 32)
                        | ((unsigned long long)(jmin << 1)) | tag;

            // spin until all 4 warp keys carry this step's tag
            unsigned long long k0, k1, k2, k3;
            while (true) {
                k0 = rk[0]; k1 = rk[1]; k2 = rk[2]; k3 = rk[3];
                unsigned long long ta = k0 & k1 & k2 & k3;
                unsigned long long to = k0 | k1 | k2 | k3;
                if (((ta & 1ull) == tag) && ((to & 1ull) == tag)) break;
            }
            unsigned long long g = k0 < k1 ? k0 : k1;
            unsigned long long h = k2 < k3 ? k2 : k3;
            if (h < g) g = h;

            float delta = funmap((unsigned int)(g >> 32));
            int   j1    = (int)(((unsigned int)g) >> 1);

            // updates (sequential per-step adds: bit-exact vs JAX; Inf stays Inf)
            #pragma unroll
            for (int c = 0; c < CPT; c++) {
                minv[c] -= delta;
                if (usedm & (1u << c)) { uacc[c] += delta; vr[c] -= delta; }
            }
            if (tid == 0) u0acc += delta;

            float4 pr = prow[j1];
            j0 = j1;
            i0 = __float_as_int(pr.x);
            if (i0 == 0) break;        // free column reached
            ui0 = pr.y; tt1 = pr.z; tt2 = pr.w;
        }

        // flush u (stores of exactly-accumulated registers)
        #pragma unroll
        for (int c = 0; c < CPT; c++)
            if (usedm & (1u << c)) u_sh[rowc[c]] = uacc[c];
        if (tid == 0) u_sh[i] = u0acc;
        __syncthreads();

        if (tid == 0) {                 // augment
            int jj = j0;
            while (jj != 0) {
                int jn = way_sh[jj];
                p_sh[jj] = (jn == 0) ? i : p_sh[jn];
                jj = jn;
            }
        }
        __syncthreads();
    }

    // a[row] = column
    #pragma unroll
    for (int c = 0; c < CPT; c++) {
        int jc = tid * CPT + c + 1;
        int pv = p_sh[jc];
        if (pv > 0) a_sh[pv - 1] = jc - 1;
    }
    __syncthreads();

    // row_ind = sort(a), col_ind = argsort(a); output f32
    if (tid < KN) {
        int av = a_sh[tid];
        int rank = 0;
        #pragma unroll 8
        for (int m = 0; m < KN; m++) rank += (a_sh[m] < av);
        out[b * KN + rank] = (float)av;
        if (write_col_ind) out[BSN * KN + b * KN + rank] = (float)tid;
    }
}

extern "C" void kernel_launch(void* const* d_in, const int* in_sizes, int n_in,
                              void* d_out, int out_size) {
    const float* in0;
    const float* in1;
    if (n_in == 1) {
        in0 = (const float*)d_in[0];
        in1 = in0 + NELEM * BSN;
    } else {
        int i0 = -1, i1 = -1;
        for (int t = 0; t < n_in; t++) {
            if (in_sizes[t] == BSN * NELEM) {
                if (i0 < 0) i0 = t;
                else if (i1 < 0) i1 = t;
            }
        }
        if (i0 < 0) { i0 = 0; i1 = 1; }
        if (i1 < 0) i1 = (i0 == 0 ? 1 : 0);
        in0 = (const float*)d_in[i0];
        in1 = (const float*)d_in[i1];
    }
    float* out = (float*)d_out;
    int write_col = (out_size >= 2 * BSN * KN) ? 1 : 0;
    hungarian_kernel<<<BSN, NT>>>(in0, in1, out, write_col);
}

// round 11
// speedup vs baseline: 1.1314x; 1.1314x over previous
#include <cuda_runtime.h>
#include <cuda_bf16.h>
#include <math.h>

#define BSN 32
#define QN 1024
#define KN 96
#define QN1 (QN + 1)
#define INFV 1000000000.0f
#define NELEM (QN * 3)   // 98304 per input
#define NT 128
#define CPT 8
#define NW (NT / 32)
#define FINF __int_as_float(0x7F800000)

__device__ __forceinline__ bool probe_is_labels(const float* x) {
    const int qs[6] = {0, 13, 95, 96, 511, 1023};
    #pragma unroll
    for (int t = 0; t < 6; t++) {
        float v = x[qs[t] * 3];
        if (v != 0.0f && v != 1.0f) return false;
    }
    return true;
}

// Bit-exact replica of XLA:CPU GenerateVF32Exp (proven R6).
__device__ __forceinline__ float xla_cpu_expf(float x_in) {
    float x = fmaxf(fminf(x_in, 88.3762626647950f), -88.3762626647949f);
    float fx = floorf(__fmaf_rn(x, 1.44269504088896341f, 0.5f));
    float tmp = __fmul_rn(0.693359375f, fx);
    float z   = __fmul_rn(-2.12194440e-4f, fx);
    x = __fsub_rn(x, tmp);
    x = __fsub_rn(x, z);
    float x2 = __fmul_rn(x, x);
    float y = __fmaf_rn(x, 1.9875691500E-4f, 1.3981999507E-3f);
    y = __fmaf_rn(y, x, 8.3334519073E-3f);
    y = __fmaf_rn(y, x, 4.1665795894E-2f);
    y = __fmaf_rn(y, x, 1.6666665459E-1f);
    y = __fmaf_rn(y, x, 5.0000001201E-1f);
    y = __fmaf_rn(y, x2, x);
    y = __fadd_rn(y, 1.0f);
    int k = (int)fx;
    float scale = __int_as_float((k + 127) << 23);
    return fmaxf(__fmul_rn(y, scale), x_in);
}

__device__ __forceinline__ float xla_sigmoid(float x) {
    float e = xla_cpu_expf(-x);
    return __fdiv_rn(1.0f, __fadd_rn(1.0f, e));
}

// monotone float -> u32 map (no NaN ties / -0.0 in our domain)
__device__ __forceinline__ unsigned int fmap(float f) {
    unsigned int u = __float_as_uint(f);
    return (u & 0x80000000u) ? ~u : (u | 0x80000000u);
}
__device__ __forceinline__ float funmap(unsigned int m) {
    unsigned int u = (m & 0x80000000u) ? (m & 0x7FFFFFFFu) : ~m;
    return __uint_as_float(u);
}

__device__ __forceinline__ unsigned int redux_min_u32(unsigned int x) {
    unsigned int r;
    asm("redux.sync.min.u32 %0, %1, 0xffffffff;" : "=r"(r) : "r"(x));
    return r;
}

__global__ __launch_bounds__(NT, 1)
void hungarian_kernel(const float* __restrict__ in0,
                      const float* __restrict__ in1,
                      float* __restrict__ out,
                      int write_col_ind) {
    __shared__ float  u_sh[KN + 1];
    __shared__ int    p_sh[QN1];
    __shared__ int    way_sh[QN1];
    __shared__ float  t1_sh[KN], t2_sh[KN];
    __shared__ float4 prow[QN1];            // {p (int bits), u[p], t1[p-1], t2[p-1]}
    __shared__ unsigned long long redk[2][NW];   // parity double buffer
    __shared__ int    a_sh[KN];
    __shared__ int    swap_flag;

    const int tid  = threadIdx.x;
    const int b    = blockIdx.x;
    const int lane = tid & 31;
    const int wid  = tid >> 5;

    if (tid == 0) {
        bool l0 = probe_is_labels(in0);
        bool l1 = probe_is_labels(in1);
        swap_flag = (l0 && !l1) ? 1 : 0;
    }
    __syncthreads();
    const float* L  = (swap_flag ? in1 : in0) + (size_t)b * NELEM;  // logits
    const float* Lb = (swap_flag ? in0 : in1) + (size_t)b * NELEM;  // labels

    // Per-thread columns: jc = tid*CPT + c + 1 (contiguous)
    float negorig[CPT], np[CPT], b1r[CPT], b2r[CPT], vr[CPT], minv[CPT], uacc[CPT];
    int   rowc[CPT], wayr[CPT];
    #pragma unroll
    for (int c = 0; c < CPT; c++) {
        int q = tid * CPT + c;
        negorig[c] = -xla_sigmoid(L[q * 3 + 0]);
        b1r[c] = L[q * 3 + 1];
        b2r[c] = L[q * 3 + 2];
        vr[c]  = 0.0f;
    }
    if (tid < KN) {
        t1_sh[tid] = Lb[tid * 3 + 1];
        t2_sh[tid] = Lb[tid * 3 + 2];
        u_sh[tid + 1] = 0.0f;
    }
    if (tid == 0) u_sh[0] = 0.0f;
    for (int idx = tid; idx < QN1; idx += NT) p_sh[idx] = 0;
    __syncthreads();

    for (int i = 1; i <= KN; i++) {
        // rebuild prow: p and u are frozen during a path (proven R7)
        for (int idx = tid; idx < QN; idx += NT) {
            int jj = idx + 1;
            int pi = p_sh[jj];
            float4 r;
            r.x = __int_as_float(pi);
            if (pi > 0) { r.y = u_sh[pi]; r.z = t1_sh[pi - 1]; r.w = t2_sh[pi - 1]; }
            else        { r.y = 0.0f; r.z = 0.0f; r.w = 0.0f; }
            prow[jj] = r;
        }

        #pragma unroll
        for (int c = 0; c < CPT; c++) {
            minv[c] = INFV; np[c] = negorig[c]; wayr[c] = 0;
        }
        unsigned int usedm = 0;
        int   j0 = 0, i0 = i;
        float ui0 = u_sh[i];
        float tt1 = t1_sh[i - 1], tt2 = t2_sh[i - 1];
        float u0acc = ui0;     // column 0 (always used), tracked by tid 0
        int par = 0;

        while (true) {
            // mark used: owner poisons working copies (np/minv = +Inf)
            unsigned int t = (unsigned int)(j0 - 1 - tid * CPT);
            if (t < CPT) {
                usedm |= (1u << t);
                #pragma unroll
                for (int c = 0; c < CPT; c++)
                    if (c == (int)t) {
                        np[c] = FINF; minv[c] = FINF;
                        uacc[c] = ui0; rowc[c] = i0;
                    }
            }

            // compute candidates (used cols give cur = +Inf); way in registers
            #pragma unroll
            for (int c = 0; c < CPT; c++) {
                float d1 = b1r[c] - tt1;
                float d2 = b2r[c] - tt2;
                float s  = fabsf(d1) + fabsf(d2);
                float cur = ((np[c] + s) - ui0) - vr[c];
                if (cur < minv[c]) wayr[c] = j0;
                minv[c] = fminf(minv[c], cur);
            }
            // thread-best: exact min tree (order-free, no rounding)
            float m01 = fminf(minv[0], minv[1]);
            float m23 = fminf(minv[2], minv[3]);
            float m45 = fminf(minv[4], minv[5]);
            float m67 = fminf(minv[6], minv[7]);
            float bestv = fminf(fminf(m01, m23), fminf(m45, m67));
            // local argmin (first c), off the inter-redux critical path
            unsigned int lj = 0x7FFFFFFFu;
            #pragma unroll
            for (int c = CPT - 1; c >= 0; c--)
                if (minv[c] == bestv) lj = (unsigned int)(tid * CPT + c + 1);

            unsigned int mb   = fmap(bestv);
            unsigned int wmin = redux_min_u32(mb);
            unsigned int jc2  = (mb == wmin) ? lj : 0x7FFFFFFFu;
            unsigned int jmin = redux_min_u32(jc2);
            if (lane == 0)
                redk[par][wid] = ((unsigned long long)wmin << 32) | jmin;
            __syncthreads();

            // cross-warp min (every thread, redundantly; parity buffer => WAR-safe)
            unsigned long long k0 = redk[par][0], k1 = redk[par][1];
            unsigned long long k2 = redk[par][2], k3 = redk[par][3];
            unsigned long long g = k0 < k1 ? k0 : k1;
            unsigned long long h = k2 < k3 ? k2 : k3;
            if (h < g) g = h;

            float delta = funmap((unsigned int)(g >> 32));
            int   j1    = (int)(unsigned int)g;

            // updates (sequential per-step adds: bit-exact vs JAX; Inf stays Inf)
            #pragma unroll
            for (int c = 0; c < CPT; c++) {
                minv[c] -= delta;
                if (usedm & (1u << c)) { uacc[c] += delta; vr[c] -= delta; }
            }
            if (tid == 0) u0acc += delta;

            float4 pr = prow[j1];
            j0 = j1;
            i0 = __float_as_int(pr.x);
            if (i0 == 0) break;        // free column reached
            ui0 = pr.y; tt1 = pr.z; tt2 = pr.w;
            par ^= 1;
        }

        // flush u and way (register-accumulated; exact sequential values)
        #pragma unroll
        for (int c = 0; c < CPT; c++) {
            way_sh[tid * CPT + c + 1] = wayr[c];
            if (usedm & (1u << c)) u_sh[rowc[c]] = uacc[c];
        }
        if (tid == 0) u_sh[i] = u0acc;
        __syncthreads();

        if (tid == 0) {                 // augment
            int jj = j0;
            while (jj != 0) {
                int jn = way_sh[jj];
                p_sh[jj] = (jn == 0) ? i : p_sh[jn];
                jj = jn;
            }
        }
        __syncthreads();
    }

    // a[row] = column
    #pragma unroll
    for (int c = 0; c < CPT; c++) {
        int jc = tid * CPT + c + 1;
        int pv = p_sh[jc];
        if (pv > 0) a_sh[pv - 1] = jc - 1;
    }
    __syncthreads();

    // row_ind = sort(a), col_ind = argsort(a); output f32
    if (tid < KN) {
        int av = a_sh[tid];
        int rank = 0;
        #pragma unroll 8
        for (int m = 0; m < KN; m++) rank += (a_sh[m] < av);
        out[b * KN + rank] = (float)av;
        if (write_col_ind) out[BSN * KN + b * KN + rank] = (float)tid;
    }
}

extern "C" void kernel_launch(void* const* d_in, const int* in_sizes, int n_in,
                              void* d_out, int out_size) {
    const float* in0;
    const float* in1;
    if (n_in == 1) {
        in0 = (const float*)d_in[0];
        in1 = in0 + NELEM * BSN;
    } else {
        int i0 = -1, i1 = -1;
        for (int t = 0; t < n_in; t++) {
            if (in_sizes[t] == BSN * NELEM) {
                if (i0 < 0) i0 = t;
                else if (i1 < 0) i1 = t;
            }
        }
        if (i0 < 0) { i0 = 0; i1 = 1; }
        if (i1 < 0) i1 = (i0 == 0 ? 1 : 0);
        in0 = (const float*)d_in[i0];
        in1 = (const float*)d_in[i1];
    }
    float* out = (float*)d_out;
    int write_col = (out_size >= 2 * BSN * KN) ? 1 : 0;
    hungarian_kernel<<<BSN, NT>>>(in0, in1, out, write_col);
}

// round 12
// speedup vs baseline: 1.2113x; 1.0707x over previous
#include <cuda_runtime.h>
#include <cuda_bf16.h>
#include <math.h>

#define BSN 32
#define QN 1024
#define KN 96
#define QN1 (QN + 1)
#define INFV 1000000000.0f
#define NELEM (QN * 3)   // 98304 per input
#define NT 128
#define CPT 8
#define NW (NT / 32)
#define FINF __int_as_float(0x7F800000)

__device__ __forceinline__ bool probe_is_labels(const float* x) {
    const int qs[6] = {0, 13, 95, 96, 511, 1023};
    #pragma unroll
    for (int t = 0; t < 6; t++) {
        float v = x[qs[t] * 3];
        if (v != 0.0f && v != 1.0f) return false;
    }
    return true;
}

// Bit-exact replica of XLA:CPU GenerateVF32Exp (proven R6).
__device__ __forceinline__ float xla_cpu_expf(float x_in) {
    float x = fmaxf(fminf(x_in, 88.3762626647950f), -88.3762626647949f);
    float fx = floorf(__fmaf_rn(x, 1.44269504088896341f, 0.5f));
    float tmp = __fmul_rn(0.693359375f, fx);
    float z   = __fmul_rn(-2.12194440e-4f, fx);
    x = __fsub_rn(x, tmp);
    x = __fsub_rn(x, z);
    float x2 = __fmul_rn(x, x);
    float y = __fmaf_rn(x, 1.9875691500E-4f, 1.3981999507E-3f);
    y = __fmaf_rn(y, x, 8.3334519073E-3f);
    y = __fmaf_rn(y, x, 4.1665795894E-2f);
    y = __fmaf_rn(y, x, 1.6666665459E-1f);
    y = __fmaf_rn(y, x, 5.0000001201E-1f);
    y = __fmaf_rn(y, x2, x);
    y = __fadd_rn(y, 1.0f);
    int k = (int)fx;
    float scale = __int_as_float((k + 127) << 23);
    return fmaxf(__fmul_rn(y, scale), x_in);
}

__device__ __forceinline__ float xla_sigmoid(float x) {
    float e = xla_cpu_expf(-x);
    return __fdiv_rn(1.0f, __fadd_rn(1.0f, e));
}

// monotone float -> u32 map (no NaN ties / -0.0 in our domain)
__device__ __forceinline__ unsigned int fmap(float f) {
    unsigned int u = __float_as_uint(f);
    return (u & 0x80000000u) ? ~u : (u | 0x80000000u);
}
__device__ __forceinline__ float funmap(unsigned int m) {
    unsigned int u = (m & 0x80000000u) ? (m & 0x7FFFFFFFu) : ~m;
    return __uint_as_float(u);
}

__device__ __forceinline__ unsigned int redux_min_u32(unsigned int x) {
    unsigned int r;
    asm("redux.sync.min.u32 %0, %1, 0xffffffff;" : "=r"(r) : "r"(x));
    return r;
}

__global__ __launch_bounds__(NT, 1)
void hungarian_kernel(const float* __restrict__ in0,
                      const float* __restrict__ in1,
                      float* __restrict__ out,
                      int write_col_ind) {
    __shared__ float  u_sh[KN + 1];
    __shared__ int    p_sh[QN1];
    __shared__ int    way_sh[QN1];
    __shared__ float  t1_sh[KN], t2_sh[KN];
    __shared__ float4 prow[QN1];            // {p (int bits), u[p], t1[p-1], t2[p-1]}
    __shared__ unsigned long long redk[2][NW];   // parity double buffer
    __shared__ int    a_sh[KN];
    __shared__ int    swap_flag;

    const int tid  = threadIdx.x;
    const int b    = blockIdx.x;
    const int lane = tid & 31;
    const int wid  = tid >> 5;

    if (tid == 0) {
        bool l0 = probe_is_labels(in0);
        bool l1 = probe_is_labels(in1);
        swap_flag = (l0 && !l1) ? 1 : 0;
    }
    __syncthreads();
    const float* L  = (swap_flag ? in1 : in0) + (size_t)b * NELEM;  // logits
    const float* Lb = (swap_flag ? in0 : in1) + (size_t)b * NELEM;  // labels

    // Per-thread columns: jc = tid*CPT + c + 1 (contiguous)
    float negorig[CPT], np[CPT], b1r[CPT], b2r[CPT], vr[CPT], minv[CPT], uacc[CPT];
    int   rowc[CPT], wayr[CPT];
    #pragma unroll
    for (int c = 0; c < CPT; c++) {
        int q = tid * CPT + c;
        negorig[c] = -xla_sigmoid(L[q * 3 + 0]);
        b1r[c] = L[q * 3 + 1];
        b2r[c] = L[q * 3 + 2];
        vr[c]  = 0.0f;
    }
    if (tid < KN) {
        t1_sh[tid] = Lb[tid * 3 + 1];
        t2_sh[tid] = Lb[tid * 3 + 2];
        u_sh[tid + 1] = 0.0f;
    }
    if (tid == 0) u_sh[0] = 0.0f;
    for (int idx = tid; idx < QN1; idx += NT) p_sh[idx] = 0;
    __syncthreads();

    for (int i = 1; i <= KN; i++) {
        // rebuild prow: p and u are frozen during a path (proven R7)
        for (int idx = tid; idx < QN; idx += NT) {
            int jj = idx + 1;
            int pi = p_sh[jj];
            float4 r;
            r.x = __int_as_float(pi);
            if (pi > 0) { r.y = u_sh[pi]; r.z = t1_sh[pi - 1]; r.w = t2_sh[pi - 1]; }
            else        { r.y = 0.0f; r.z = 0.0f; r.w = 0.0f; }
            prow[jj] = r;
        }

        #pragma unroll
        for (int c = 0; c < CPT; c++) {
            minv[c] = INFV; np[c] = negorig[c]; wayr[c] = 0;
            uacc[c] = 0.0f; rowc[c] = 0;
        }
        unsigned int usedm = 0;
        int   j0 = 0, i0 = i;
        float ui0 = u_sh[i];
        float tt1 = t1_sh[i - 1], tt2 = t2_sh[i - 1];
        float u0acc = ui0;     // identical in ALL threads; tid 0's store used
        int par = 0;

        while (true) {
            // branchless used-mark: exactly one thread has t in [0,CPT)
            unsigned int t = (unsigned int)(j0 - 1 - tid * CPT);
            if (t < CPT) usedm |= (1u << t);   // scalar, predicated (no BSSY)
            #pragma unroll
            for (int c = 0; c < CPT; c++) {
                bool pd = ((unsigned int)c == t);
                np[c]   = pd ? FINF : np[c];
                minv[c] = pd ? FINF : minv[c];
                uacc[c] = pd ? ui0  : uacc[c];
                rowc[c] = pd ? i0   : rowc[c];
            }

            // compute candidates (used cols give cur = +Inf); way in registers
            #pragma unroll
            for (int c = 0; c < CPT; c++) {
                float d1 = b1r[c] - tt1;
                float d2 = b2r[c] - tt2;
                float s  = fabsf(d1) + fabsf(d2);
                float cur = ((np[c] + s) - ui0) - vr[c];
                if (cur < minv[c]) wayr[c] = j0;
                minv[c] = fminf(minv[c], cur);
            }
            // thread-best: exact min tree
            float m01 = fminf(minv[0], minv[1]);
            float m23 = fminf(minv[2], minv[3]);
            float m45 = fminf(minv[4], minv[5]);
            float m67 = fminf(minv[6], minv[7]);
            float bestv = fminf(fminf(m01, m23), fminf(m45, m67));
            // local argmin (first c), off the inter-redux critical path
            unsigned int lj = 0x7FFFFFFFu;
            #pragma unroll
            for (int c = CPT - 1; c >= 0; c--)
                if (minv[c] == bestv) lj = (unsigned int)(tid * CPT + c + 1);

            unsigned int mb   = fmap(bestv);
            unsigned int wmin = redux_min_u32(mb);
            unsigned int jc2  = (mb == wmin) ? lj : 0x7FFFFFFFu;
            unsigned int jmin = redux_min_u32(jc2);

            // speculative prefetch of this warp's candidate (prow frozen => safe;
            // overlaps the barrier wait)
            float4 pr = prow[jmin];

            if (lane == 0)
                redk[par][wid] = ((unsigned long long)wmin << 32) | jmin;
            __syncthreads();

            // cross-warp min (every thread, redundantly; parity buffer => WAR-safe)
            unsigned long long k0 = redk[par][0], k1 = redk[par][1];
            unsigned long long k2 = redk[par][2], k3 = redk[par][3];
            unsigned long long g = k0 < k1 ? k0 : k1;
            unsigned long long h = k2 < k3 ? k2 : k3;
            if (h < g) g = h;

            float delta = funmap((unsigned int)(g >> 32));
            int   j1    = (int)(unsigned int)g;
            if (j1 != (int)jmin) pr = prow[j1];   // warp-uniform branch

            // updates (sequential per-step adds: bit-exact vs JAX; Inf stays Inf)
            #pragma unroll
            for (int c = 0; c < CPT; c++) {
                minv[c] -= delta;
                if (usedm & (1u << c)) { uacc[c] += delta; vr[c] -= delta; }
            }
            u0acc += delta;    // all threads, branchless

            j0 = j1;
            i0 = __float_as_int(pr.x);
            if (i0 == 0) break;        // free column reached (uniform)
            ui0 = pr.y; tt1 = pr.z; tt2 = pr.w;
            par ^= 1;
        }

        // flush u and way (register-accumulated; exact sequential values)
        #pragma unroll
        for (int c = 0; c < CPT; c++) {
            way_sh[tid * CPT + c + 1] = wayr[c];
            if (usedm & (1u << c)) u_sh[rowc[c]] = uacc[c];
        }
        if (tid == 0) u_sh[i] = u0acc;
        __syncthreads();

        if (tid == 0) {                 // augment
            int jj = j0;
            while (jj != 0) {
                int jn = way_sh[jj];
                p_sh[jj] = (jn == 0) ? i : p_sh[jn];
                jj = jn;
            }
        }
        __syncthreads();
    }

    // a[row] = column
    #pragma unroll
    for (int c = 0; c < CPT; c++) {
        int jc = tid * CPT + c + 1;
        int pv = p_sh[jc];
        if (pv > 0) a_sh[pv - 1] = jc - 1;
    }
    __syncthreads();

    // row_ind = sort(a), col_ind = argsort(a); output f32
    if (tid < KN) {
        int av = a_sh[tid];
        int rank = 0;
        #pragma unroll 8
        for (int m = 0; m < KN; m++) rank += (a_sh[m] < av);
        out[b * KN + rank] = (float)av;
        if (write_col_ind) out[BSN * KN + b * KN + rank] = (float)tid;
    }
}

extern "C" void kernel_launch(void* const* d_in, const int* in_sizes, int n_in,
                              void* d_out, int out_size) {
    const float* in0;
    const float* in1;
    if (n_in == 1) {
        in0 = (const float*)d_in[0];
        in1 = in0 + NELEM * BSN;
    } else {
        int i0 = -1, i1 = -1;
        for (int t = 0; t < n_in; t++) {
            if (in_sizes[t] == BSN * NELEM) {
                if (i0 < 0) i0 = t;
                else if (i1 < 0) i1 = t;
            }
        }
        if (i0 < 0) { i0 = 0; i1 = 1; }
        if (i1 < 0) i1 = (i0 == 0 ? 1 : 0);
        in0 = (const float*)d_in[i0];
        in1 = (const float*)d_in[i1];
    }
    float* out = (float*)d_out;
    int write_col = (out_size >= 2 * BSN * KN) ? 1 : 0;
    hungarian_kernel<<<BSN, NT>>>(in0, in1, out, write_col);
}